// round 2
// baseline (speedup 1.0000x reference)
#include <cuda_runtime.h>
#include <math.h>

#define BB 4
#define LL 2048
#define KK 30
#define HID 128
#define NHD 4
#define NLAY 3
#define NNODE (BB*LL)        /* 8192  */
#define NE (NNODE*KK)        /* 245760 */
#define EPSX 1e-6f

// ---------------- scratch (static device globals; no allocation) ----------
__device__ float g_hV[NNODE*HID];          // 4 MB
__device__ float g_Q[NNODE*HID];           // 4 MB
__device__ float g_hE[NE*HID];             // 126 MB
__device__ float g_Vh[NE*HID];             // 126 MB
__device__ float g_K1[NE*HID];             // 126 MB
__device__ float g_logits[NNODE*NHD*KK];   // 3.9 MB

// ---------------- packed f32x2 FMA --------------------------------------
__device__ __forceinline__ float2 ffma2(float2 d, float2 a, float2 b) {
    unsigned long long du = *reinterpret_cast<unsigned long long*>(&d);
    unsigned long long au = *reinterpret_cast<unsigned long long*>(&a);
    unsigned long long bu = *reinterpret_cast<unsigned long long*>(&b);
    asm("fma.rn.f32x2 %0, %1, %2, %0;" : "+l"(du) : "l"(au), "l"(bu));
    return *reinterpret_cast<float2*>(&du);
}

// =========================================================================
// Big-tile GEMM machinery: CTA = 256 rows x 128 cols, 256 threads,
// thread tile = 16 rows x 8 cols (4 f32x2 col-pairs).
// a_s: [256][132] row-major (pad 4), w_s: [128][128] row-major.
// =========================================================================
#define AS_STRIDE 132
#define AS_FLOATS (256*AS_STRIDE)
#define SMN ((AS_FLOATS + 128*128)*4)

__device__ __forceinline__ void stage_w(float* w_s, const float* __restrict__ W, int t) {
    #pragma unroll
    for (int i = 0; i < 16; ++i)
        reinterpret_cast<float4*>(w_s)[t + i*256] =
            reinterpret_cast<const float4*>(W)[t + i*256];
}

__device__ __forceinline__ void stage_a_rows(float* a_s, const float* __restrict__ src, int t) {
    int lane = t & 31, w = t >> 5;
    #pragma unroll
    for (int rr = 0; rr < 32; ++rr) {
        int row = w + rr*8;
        float4 v = *reinterpret_cast<const float4*>(&src[row*128 + lane*4]);
        *reinterpret_cast<float4*>(&a_s[row*AS_STRIDE + lane*4]) = v;
    }
}

__device__ __forceinline__ void stage_a_gather(float* a_s, const float* __restrict__ basep,
                                               const int* grow, int t) {
    int lane = t & 31, w = t >> 5;
    #pragma unroll
    for (int rr = 0; rr < 32; ++rr) {
        int row = w + rr*8;
        const float* src = basep + grow[row]*128;
        float4 v = *reinterpret_cast<const float4*>(&src[lane*4]);
        *reinterpret_cast<float4*>(&a_s[row*AS_STRIDE + lane*4]) = v;
    }
}

// acc[r][c] covers row tr*16+r, cols (tc*8 + 2c, tc*8 + 2c + 1)
__device__ __forceinline__ void gemm_core(const float* __restrict__ a_s,
                                          const float* __restrict__ w_s,
                                          int tr, int tc, float2 acc[16][4]) {
    const float* ap = a_s + tr*16*AS_STRIDE;
    const float* wp = w_s + tc*8;
    #pragma unroll 1
    for (int j = 0; j < 128; j += 2) {
        float2 a2[16];
        #pragma unroll
        for (int r = 0; r < 16; ++r)
            a2[r] = *reinterpret_cast<const float2*>(&ap[r*AS_STRIDE + j]);
        #pragma unroll
        for (int u = 0; u < 2; ++u) {
            float4 wA = *reinterpret_cast<const float4*>(&wp[(j+u)*128]);
            float4 wB = *reinterpret_cast<const float4*>(&wp[(j+u)*128 + 4]);
            float2 wv0 = make_float2(wA.x, wA.y), wv1 = make_float2(wA.z, wA.w);
            float2 wv2 = make_float2(wB.x, wB.y), wv3 = make_float2(wB.z, wB.w);
            #pragma unroll
            for (int r = 0; r < 16; ++r) {
                float av = u ? a2[r].y : a2[r].x;
                float2 ad = make_float2(av, av);
                acc[r][0] = ffma2(acc[r][0], ad, wv0);
                acc[r][1] = ffma2(acc[r][1], ad, wv1);
                acc[r][2] = ffma2(acc[r][2], ad, wv2);
                acc[r][3] = ffma2(acc[r][3], ad, wv3);
            }
        }
    }
}

// =========================================================================
// k_proj: out = in @ W (+bias). 256 rows / CTA. Also used for K1.
// =========================================================================
__global__ __launch_bounds__(256, 1) void k_proj(const float* __restrict__ in,
                                                 const float* __restrict__ W,
                                                 const float* __restrict__ bias,
                                                 float* __restrict__ out) {
    extern __shared__ float sm[];
    float* a_s = sm; float* w_s = sm + AS_FLOATS;
    int t = threadIdx.x, tr = t >> 4, tc = t & 15;
    int base = blockIdx.x * 256;

    stage_w(w_s, W, t);
    stage_a_rows(a_s, in + (long)base*128, t);
    __syncthreads();

    float2 acc[16][4] = {};
    gemm_core(a_s, w_s, tr, tc, acc);

    float4 b0 = make_float4(0.f,0.f,0.f,0.f), b1 = b0;
    if (bias) {
        b0 = *reinterpret_cast<const float4*>(&bias[tc*8]);
        b1 = *reinterpret_cast<const float4*>(&bias[tc*8+4]);
    }
    #pragma unroll
    for (int r = 0; r < 16; ++r) {
        int row = base + tr*16 + r;
        float4 o0 = make_float4(acc[r][0].x+b0.x, acc[r][0].y+b0.y,
                                acc[r][1].x+b0.z, acc[r][1].y+b0.w);
        float4 o1 = make_float4(acc[r][2].x+b1.x, acc[r][2].y+b1.y,
                                acc[r][3].x+b1.z, acc[r][3].y+b1.w);
        *reinterpret_cast<float4*>(&out[row*128 + tc*8])     = o0;
        *reinterpret_cast<float4*>(&out[row*128 + tc*8 + 4]) = o1;
    }
}

// =========================================================================
// k_logits: k2 = gather(hV) @ Wk2; logits = sum(Q*K1*k2)/32 per head.
// =========================================================================
__global__ __launch_bounds__(256, 1) void k_logits(const int* __restrict__ E_idx,
                                                   const float* __restrict__ Wk2) {
    extern __shared__ float sm[];
    float* a_s = sm; float* w_s = sm + AS_FLOATS;
    __shared__ int grow[256];
    int t = threadIdx.x, tr = t >> 4, tc = t & 15;
    int base = blockIdx.x * 256;

    {
        int e = base + t;
        int b = e / (LL*KK);
        grow[t] = b * LL + E_idx[e];
    }
    stage_w(w_s, Wk2, t);
    __syncthreads();
    stage_a_gather(a_s, g_hV, grow, t);
    __syncthreads();

    float2 acc[16][4] = {};
    gemm_core(a_s, w_s, tr, tc, acc);

    #pragma unroll
    for (int r = 0; r < 16; ++r) {
        int e = base + tr*16 + r;
        int node = e / KK;
        int k = e - node*KK;
        float4 q0  = *reinterpret_cast<const float4*>(&g_Q[node*128 + tc*8]);
        float4 q1  = *reinterpret_cast<const float4*>(&g_Q[node*128 + tc*8 + 4]);
        float4 k10 = *reinterpret_cast<const float4*>(&g_K1[e*128 + tc*8]);
        float4 k11 = *reinterpret_cast<const float4*>(&g_K1[e*128 + tc*8 + 4]);
        float s = q0.x*k10.x*acc[r][0].x + q0.y*k10.y*acc[r][0].y
                + q0.z*k10.z*acc[r][1].x + q0.w*k10.w*acc[r][1].y
                + q1.x*k11.x*acc[r][2].x + q1.y*k11.y*acc[r][2].y
                + q1.z*k11.z*acc[r][3].x + q1.w*k11.w*acc[r][3].y;
        s += __shfl_xor_sync(0xffffffffu, s, 1);
        s += __shfl_xor_sync(0xffffffffu, s, 2);
        if ((tc & 3) == 0)
            g_logits[(node*NHD + (tc >> 2))*KK + k] = s * (1.0f/32.0f);
    }
}

// =========================================================================
// k_vh: Vh = hE @ Wv[0:128] + gather(hV) @ Wv[128:256]
// =========================================================================
__global__ __launch_bounds__(256, 1) void k_vh(const int* __restrict__ E_idx,
                                               const float* __restrict__ Wv) {
    extern __shared__ float sm[];
    float* a_s = sm; float* w_s = sm + AS_FLOATS;
    __shared__ int grow[256];
    int t = threadIdx.x, tr = t >> 4, tc = t & 15;
    int base = blockIdx.x * 256;

    {
        int e = base + t;
        int b = e / (LL*KK);
        grow[t] = b * LL + E_idx[e];
    }
    stage_w(w_s, Wv, t);
    stage_a_rows(a_s, g_hE + (long)base*128, t);
    __syncthreads();

    float2 acc[16][4] = {};
    gemm_core(a_s, w_s, tr, tc, acc);
    __syncthreads();

    stage_w(w_s, Wv + 128*128, t);
    stage_a_gather(a_s, g_hV, grow, t);
    __syncthreads();
    gemm_core(a_s, w_s, tr, tc, acc);

    #pragma unroll
    for (int r = 0; r < 16; ++r) {
        int row = base + tr*16 + r;
        float4 o0 = make_float4(acc[r][0].x, acc[r][0].y, acc[r][1].x, acc[r][1].y);
        float4 o1 = make_float4(acc[r][2].x, acc[r][2].y, acc[r][3].x, acc[r][3].y);
        *reinterpret_cast<float4*>(&g_Vh[row*128 + tc*8])     = o0;
        *reinterpret_cast<float4*>(&g_Vh[row*128 + tc*8 + 4]) = o1;
    }
}

// =========================================================================
// k_edge_up: h_E = LN(relu([hE, gather(hV), self(hV)] @ fc1 + b))
// =========================================================================
__global__ __launch_bounds__(256, 1) void k_edge_up(const int* __restrict__ E_idx,
                                                    const float* __restrict__ fc1w,
                                                    const float* __restrict__ fc1b,
                                                    const float* __restrict__ ng,
                                                    const float* __restrict__ nb) {
    extern __shared__ float sm[];
    float* a_s = sm; float* w_s = sm + AS_FLOATS;
    __shared__ int grow[256];
    int t = threadIdx.x, tr = t >> 4, tc = t & 15;
    int base = blockIdx.x * 256;

    {
        int e = base + t;
        int b = e / (LL*KK);
        grow[t] = b * LL + E_idx[e];
    }
    stage_w(w_s, fc1w, t);
    stage_a_rows(a_s, g_hE + (long)base*128, t);
    __syncthreads();

    float2 acc[16][4] = {};
    gemm_core(a_s, w_s, tr, tc, acc);
    __syncthreads();

    stage_w(w_s, fc1w + 128*128, t);
    stage_a_gather(a_s, g_hV, grow, t);
    __syncthreads();
    gemm_core(a_s, w_s, tr, tc, acc);
    __syncthreads();

    stage_w(w_s, fc1w + 2*128*128, t);
    {   // self hV rows: node = (base+row)/KK
        int lane = t & 31, w = t >> 5;
        #pragma unroll
        for (int rr = 0; rr < 32; ++rr) {
            int row = w + rr*8;
            int node = (base + row) / KK;
            float4 v = *reinterpret_cast<const float4*>(&g_hV[node*128 + lane*4]);
            *reinterpret_cast<float4*>(&a_s[row*AS_STRIDE + lane*4]) = v;
        }
    }
    __syncthreads();
    gemm_core(a_s, w_s, tr, tc, acc);

    float4 bb0 = *reinterpret_cast<const float4*>(&fc1b[tc*8]);
    float4 bb1 = *reinterpret_cast<const float4*>(&fc1b[tc*8+4]);
    float4 gg0 = *reinterpret_cast<const float4*>(&ng[tc*8]);
    float4 gg1 = *reinterpret_cast<const float4*>(&ng[tc*8+4]);
    float4 nb0 = *reinterpret_cast<const float4*>(&nb[tc*8]);
    float4 nb1 = *reinterpret_cast<const float4*>(&nb[tc*8+4]);

    #pragma unroll
    for (int r = 0; r < 16; ++r) {
        int row = base + tr*16 + r;
        float x0 = fmaxf(acc[r][0].x + bb0.x, 0.f);
        float x1 = fmaxf(acc[r][0].y + bb0.y, 0.f);
        float x2 = fmaxf(acc[r][1].x + bb0.z, 0.f);
        float x3 = fmaxf(acc[r][1].y + bb0.w, 0.f);
        float x4 = fmaxf(acc[r][2].x + bb1.x, 0.f);
        float x5 = fmaxf(acc[r][2].y + bb1.y, 0.f);
        float x6 = fmaxf(acc[r][3].x + bb1.z, 0.f);
        float x7 = fmaxf(acc[r][3].y + bb1.w, 0.f);
        float s  = x0+x1+x2+x3+x4+x5+x6+x7;
        float s2 = x0*x0+x1*x1+x2*x2+x3*x3+x4*x4+x5*x5+x6*x6+x7*x7;
        #pragma unroll
        for (int o = 8; o > 0; o >>= 1) {   // reduce across 16 tc lanes (half-warp)
            s  += __shfl_xor_sync(0xffffffffu, s,  o);
            s2 += __shfl_xor_sync(0xffffffffu, s2, o);
        }
        float mu  = s * (1.f/128.f);
        float var = fmaxf((s2 - 128.f*mu*mu) * (1.f/127.f), 0.f);
        float rs  = 1.f / (sqrtf(var + EPSX) + EPSX);
        float4 o0, o1;
        o0.x = gg0.x*(x0-mu)*rs + nb0.x;  o0.y = gg0.y*(x1-mu)*rs + nb0.y;
        o0.z = gg0.z*(x2-mu)*rs + nb0.z;  o0.w = gg0.w*(x3-mu)*rs + nb0.w;
        o1.x = gg1.x*(x4-mu)*rs + nb1.x;  o1.y = gg1.y*(x5-mu)*rs + nb1.y;
        o1.z = gg1.z*(x6-mu)*rs + nb1.z;  o1.w = gg1.w*(x7-mu)*rs + nb1.w;
        *reinterpret_cast<float4*>(&g_hE[row*128 + tc*8])     = o0;
        *reinterpret_cast<float4*>(&g_hE[row*128 + tc*8 + 4]) = o1;
    }
}

// =========================================================================
// k_attn (unchanged from R1): softmax, attend*Vh, @Wo, residual+LN.
// =========================================================================
__device__ __forceinline__ void stage_mat128(float* ws, const float* __restrict__ W,
                                             int t, int nthreads) {
    for (int i = t; i < (128*128)/4; i += nthreads)
        reinterpret_cast<float4*>(ws)[i] = reinterpret_cast<const float4*>(W)[i];
}
__device__ __forceinline__ void tile_fma(const float* a_s, const float* w_s,
                                         int n0, int c0, float2 acc[4][2]) {
    #pragma unroll 8
    for (int j = 0; j < 128; ++j) {
        float2 w0 = *reinterpret_cast<const float2*>(&w_s[j*128 + c0]);
        float2 w1 = *reinterpret_cast<const float2*>(&w_s[j*128 + c0 + 2]);
        #pragma unroll
        for (int r = 0; r < 4; ++r) {
            float a = a_s[(n0 + r)*128 + j];
            float2 a2 = make_float2(a, a);
            acc[r][0] = ffma2(acc[r][0], a2, w0);
            acc[r][1] = ffma2(acc[r][1], a2, w1);
        }
    }
}

__global__ __launch_bounds__(256) void k_attn(const int* __restrict__ E_idx,
                                              const float* __restrict__ mask,
                                              const float* __restrict__ Wo,
                                              const float* __restrict__ lng,
                                              const float* __restrict__ lnb) {
    extern __shared__ float sm[];
    float* w_s = sm;
    float* a_s = sm + 128*128;
    __shared__ float att_s[32*NHD*KK];
    int t = threadIdx.x, tx = t & 31, ty = t >> 5;
    int n0 = ty * 4, c0 = tx * 4;
    int base = blockIdx.x * 32;

    if (t < 128) {
        int nn = t >> 2, h = t & 3;
        int node = base + nn;
        int b = node / LL;
        float msel = mask[node];
        const int* eidx = &E_idx[node*KK];
        const float* lg = &g_logits[(node*NHD + h)*KK];
        float mk[KK], lv[KK];
        float mx = -3.4e38f;
        #pragma unroll
        for (int k = 0; k < KK; ++k) {
            int gi = b * LL + eidx[k];
            mk[k] = msel * mask[gi];
            lv[k] = lg[k];
            if (mk[k] > 0.f && lv[k] > mx) mx = lv[k];
        }
        float s = 0.f;
        #pragma unroll
        for (int k = 0; k < KK; ++k) {
            float e = (mk[k] > 0.f) ? __expf(lv[k] - mx) : 0.f;
            lv[k] = e; s += e;
        }
        float inv = (s > 0.f) ? (1.f / s) : 0.f;
        #pragma unroll
        for (int k = 0; k < KK; ++k)
            att_s[nn*(NHD*KK) + h*KK + k] = mk[k] * lv[k] * inv;
    }
    __syncthreads();

    #pragma unroll
    for (int r = 0; r < 4; ++r) {
        int nn = n0 + r;
        float4 u = make_float4(0.f, 0.f, 0.f, 0.f);
        const float* vh = &g_Vh[(long)(base + nn)*KK*128 + c0];
        const float* at = &att_s[nn*(NHD*KK) + (tx >> 3)*KK];
        #pragma unroll 6
        for (int k = 0; k < KK; ++k) {
            float a = at[k];
            float4 v = *reinterpret_cast<const float4*>(&vh[k*128]);
            u.x += a * v.x; u.y += a * v.y; u.z += a * v.z; u.w += a * v.w;
        }
        *reinterpret_cast<float4*>(&a_s[nn*128 + c0]) = u;
    }
    stage_mat128(w_s, Wo, t, 256);
    __syncthreads();

    float2 acc[4][2] = {};
    tile_fma(a_s, w_s, n0, c0, acc);

    float4 gv  = *reinterpret_cast<const float4*>(&lng[c0]);
    float4 bv2 = *reinterpret_cast<const float4*>(&lnb[c0]);
    #pragma unroll
    for (int r = 0; r < 4; ++r) {
        int node = base + n0 + r;
        float4 hv = *reinterpret_cast<const float4*>(&g_hV[node*128 + c0]);
        float x0 = hv.x + acc[r][0].x, x1 = hv.y + acc[r][0].y;
        float x2 = hv.z + acc[r][1].x, x3 = hv.w + acc[r][1].y;
        float s  = x0 + x1 + x2 + x3;
        float s2 = x0*x0 + x1*x1 + x2*x2 + x3*x3;
        #pragma unroll
        for (int o = 16; o > 0; o >>= 1) {
            s  += __shfl_xor_sync(0xffffffffu, s,  o);
            s2 += __shfl_xor_sync(0xffffffffu, s2, o);
        }
        float mu  = s * (1.f / 128.f);
        float var = fmaxf((s2 - 128.f * mu * mu) * (1.f / 127.f), 0.f);
        float rs  = 1.f / (sqrtf(var + EPSX) + EPSX);
        float m   = mask[node];
        float4 o4;
        o4.x = m * (gv.x * (x0 - mu) * rs + bv2.x);
        o4.y = m * (gv.y * (x1 - mu) * rs + bv2.y);
        o4.z = m * (gv.z * (x2 - mu) * rs + bv2.z);
        o4.w = m * (gv.w * (x3 - mu) * rs + bv2.w);
        *reinterpret_cast<float4*>(&g_hV[node*128 + c0]) = o4;
    }
}

__global__ void k_copy(float* __restrict__ out) {
    int i = blockIdx.x * blockDim.x + threadIdx.x;
    reinterpret_cast<float4*>(out)[i] = reinterpret_cast<const float4*>(g_hV)[i];
}

// =========================================================================
extern "C" void kernel_launch(void* const* d_in, const int* in_sizes, int n_in,
                              void* d_out, int out_size) {
    const float* V      = (const float*)d_in[0];
    const float* E      = (const float*)d_in[1];
    const int*   E_idx  = (const int*)  d_in[2];
    const float* mask   = (const float*)d_in[3];
    const float* Ws_w   = (const float*)d_in[4];
    const float* Ws_b   = (const float*)d_in[5];
    const float* Wt_w   = (const float*)d_in[6];
    const float* Wt_b   = (const float*)d_in[7];
    const float* Wq     = (const float*)d_in[8];
    const float* Wk1    = (const float*)d_in[9];
    const float* Wk2    = (const float*)d_in[10];
    const float* Wv     = (const float*)d_in[11];
    const float* Wo     = (const float*)d_in[12];
    const float* ln_g   = (const float*)d_in[13];
    const float* ln_b   = (const float*)d_in[14];
    const float* fc1_w  = (const float*)d_in[15];
    const float* fc1_b  = (const float*)d_in[16];
    const float* norm_g = (const float*)d_in[17];
    const float* norm_b = (const float*)d_in[18];

    const int SMA = (128*128 + 32*128) * 4;
    cudaFuncSetAttribute(k_proj,    cudaFuncAttributeMaxDynamicSharedMemorySize, SMN);
    cudaFuncSetAttribute(k_logits,  cudaFuncAttributeMaxDynamicSharedMemorySize, SMN);
    cudaFuncSetAttribute(k_vh,      cudaFuncAttributeMaxDynamicSharedMemorySize, SMN);
    cudaFuncSetAttribute(k_edge_up, cudaFuncAttributeMaxDynamicSharedMemorySize, SMN);
    cudaFuncSetAttribute(k_attn,    cudaFuncAttributeMaxDynamicSharedMemorySize, SMA);

    void *phV = nullptr, *pQ = nullptr, *phE = nullptr, *pK1 = nullptr;
    cudaGetSymbolAddress(&phV, g_hV);
    cudaGetSymbolAddress(&pQ,  g_Q);
    cudaGetSymbolAddress(&phE, g_hE);
    cudaGetSymbolAddress(&pK1, g_K1);

    k_proj<<<NNODE/256, 256, SMN>>>(V, Ws_w, Ws_b, (float*)phV);
    k_proj<<<NE/256,    256, SMN>>>(E, Wt_w, Wt_b, (float*)phE);

    for (int i = 0; i < NLAY; ++i) {
        k_proj<<<NNODE/256, 256, SMN>>>((const float*)phV, Wq + i*128*128,
                                        nullptr, (float*)pQ);
        k_proj<<<NE/256, 256, SMN>>>((const float*)phE, Wk1 + i*128*128,
                                     nullptr, (float*)pK1);
        k_logits<<<NE/256, 256, SMN>>>(E_idx, Wk2 + i*128*128);
        k_vh<<<NE/256, 256, SMN>>>(E_idx, Wv + i*2*128*128);
        k_attn<<<NNODE/32, 256, SMA>>>(E_idx, mask, Wo + i*128*128,
                                       ln_g + i*128, ln_b + i*128);
        k_edge_up<<<NE/256, 256, SMN>>>(E_idx, fc1_w, fc1_b, norm_g, norm_b);
    }

    k_copy<<<(NNODE*HID/4)/256, 256>>>((float*)d_out);
    (void)in_sizes; (void)n_in; (void)out_size;
}

// round 5
// speedup vs baseline: 3.8591x; 3.8591x over previous
#include <cuda_runtime.h>
#include <cuda_bf16.h>
#include <stdint.h>
#include <math.h>

#define BB 4
#define LL 2048
#define KK 30
#define NHD 4
#define NLAY 3
#define NNODE (BB*LL)        /* 8192   */
#define NE (NNODE*KK)        /* 245760 */
#define EPSX 1e-6f

// ==================== device scratch (static, no allocation) ====================
__device__ float g_hV[NNODE*128];
__device__ float g_Q[NNODE*128];
__device__ float g_Vh[(size_t)NE*128];
__device__ float g_logits[(size_t)NNODE*NHD*KK];
__device__ __nv_bfloat16 g_wbhi[23*16384], g_wblo[23*16384];   // weights [n][k] bf16
__device__ uint4 g_hVhi[NNODE*16], g_hVlo[NNODE*16];
__device__ uint4 g_Vinhi[NNODE*16], g_Vinlo[NNODE*16];
__device__ uint4 g_Einhi[(size_t)NE*16], g_Einlo[(size_t)NE*16];
__device__ uint4 g_hEhi[(size_t)NE*16],  g_hElo[(size_t)NE*16];

// ==================== helpers ====================
__device__ __forceinline__ uint32_t smem_u32(const void* p) {
    uint32_t a;
    asm("{ .reg .u64 tmp; cvta.to.shared.u64 tmp, %1; cvt.u32.u64 %0, tmp; }"
        : "=r"(a) : "l"(p));
    return a;
}
__device__ __forceinline__ void ldsm4(uint32_t r[4], uint32_t addr) {
    asm volatile("ldmatrix.sync.aligned.m8n8.x4.shared.b16 {%0,%1,%2,%3}, [%4];"
        : "=r"(r[0]), "=r"(r[1]), "=r"(r[2]), "=r"(r[3]) : "r"(addr));
}
__device__ __forceinline__ void mma16816(float c[4], const uint32_t a[4], const uint32_t b[2]) {
    asm volatile("mma.sync.aligned.m16n8k16.row.col.f32.bf16.bf16.f32 "
        "{%0,%1,%2,%3}, {%4,%5,%6,%7}, {%8,%9}, {%0,%1,%2,%3};"
        : "+f"(c[0]), "+f"(c[1]), "+f"(c[2]), "+f"(c[3])
        : "r"(a[0]), "r"(a[1]), "r"(a[2]), "r"(a[3]), "r"(b[0]), "r"(b[1]));
}
__device__ __forceinline__ void hilo2(float x, float y, uint32_t& h, uint32_t& l) {
    __nv_bfloat16 hx = __float2bfloat16_rn(x), hy = __float2bfloat16_rn(y);
    __nv_bfloat16 lx = __float2bfloat16_rn(x - __bfloat162float(hx));
    __nv_bfloat16 ly = __float2bfloat16_rn(y - __bfloat162float(hy));
    h = (uint32_t)__bfloat16_as_ushort(hx) | ((uint32_t)__bfloat16_as_ushort(hy) << 16);
    l = (uint32_t)__bfloat16_as_ushort(lx) | ((uint32_t)__bfloat16_as_ushort(ly) << 16);
}
__device__ __forceinline__ void hilo4(float4 v, uint2& h, uint2& l) {
    hilo2(v.x, v.y, h.x, l.x);
    hilo2(v.z, v.w, h.y, l.y);
}

// ==================== smem layout (bf16 elems), stride 136 pads to 272B rows ====
#define ASTRIDE 136
#define OFF_AH 0
#define OFF_AL (128*ASTRIDE)
#define OFF_WH (2*128*ASTRIDE)
#define OFF_WL (3*128*ASTRIDE)
#define SM_MMA (4*128*ASTRIDE*2)     /* 139264 bytes */

__device__ __forceinline__ void stage_a(__nv_bfloat16* smb, const uint4* ghi,
                                        const uint4* glo, const int* grow,
                                        long base, int t) {
    char* dh = (char*)smb + OFF_AH*2;
    char* dl = (char*)smb + OFF_AL*2;
    #pragma unroll
    for (int i = 0; i < 8; ++i) {
        int idx = t + 256*i;
        int row = idx >> 4, c = idx & 15;
        long gr = grow ? (long)grow[row] : (base + row);
        *(uint4*)(dh + row*272 + c*16) = ghi[gr*16 + c];
        *(uint4*)(dl + row*272 + c*16) = glo[gr*16 + c];
    }
}
__device__ __forceinline__ void stage_w(__nv_bfloat16* smb, int block, int t) {
    const uint4* sh = (const uint4*)(g_wbhi + (size_t)block*16384);
    const uint4* sl = (const uint4*)(g_wblo + (size_t)block*16384);
    char* dh = (char*)smb + OFF_WH*2;
    char* dl = (char*)smb + OFF_WL*2;
    #pragma unroll
    for (int i = 0; i < 8; ++i) {
        int idx = t + 256*i;
        int row = idx >> 4, c = idx & 15;
        *(uint4*)(dh + row*272 + c*16) = sh[idx];
        *(uint4*)(dl + row*272 + c*16) = sl[idx];
    }
}

// 3-term split GEMM: acc += A(hi+lo) @ W(hi+lo)^T (dropping lo*lo)
// warp tile 32x64: rows 32*wr.., cols 64*wc..
__device__ __forceinline__ void gemm3(uint32_t sb, int lane, int wr, int wc,
                                      float acc[2][8][4]) {
    uint32_t arow = (uint32_t)(32*wr + (lane & 15));
    uint32_t acol = (uint32_t)((lane >> 4) << 3);
    uint32_t brow = (uint32_t)(64*wc + (lane & 7) + ((lane >> 4) << 3));
    uint32_t bcol = (uint32_t)(((lane >> 3) & 1) << 3);
    #pragma unroll 2
    for (int ks = 0; ks < 8; ++ks) {
        uint32_t k0 = (uint32_t)(ks*16);
        uint32_t ah[2][4], al[2][4];
        #pragma unroll
        for (int mi = 0; mi < 2; ++mi) {
            uint32_t off = ((arow + 16u*mi)*ASTRIDE + k0 + acol)*2u;
            ldsm4(ah[mi], sb + OFF_AH*2 + off);
            ldsm4(al[mi], sb + OFF_AL*2 + off);
        }
        uint32_t bh[8][2], bl[8][2];
        #pragma unroll
        for (int jp = 0; jp < 4; ++jp) {
            uint32_t off = ((brow + 16u*jp)*ASTRIDE + k0 + bcol)*2u;
            uint32_t r[4];
            ldsm4(r, sb + OFF_WH*2 + off);
            bh[2*jp][0] = r[0]; bh[2*jp][1] = r[1];
            bh[2*jp+1][0] = r[2]; bh[2*jp+1][1] = r[3];
            ldsm4(r, sb + OFF_WL*2 + off);
            bl[2*jp][0] = r[0]; bl[2*jp][1] = r[1];
            bl[2*jp+1][0] = r[2]; bl[2*jp+1][1] = r[3];
        }
        #pragma unroll
        for (int mi = 0; mi < 2; ++mi)
            #pragma unroll
            for (int j = 0; j < 8; ++j) {
                mma16816(acc[mi][j], ah[mi], bh[j]);
                mma16816(acc[mi][j], ah[mi], bl[j]);
                mma16816(acc[mi][j], al[mi], bh[j]);
            }
    }
}

// ==================== conversion kernels ====================
__global__ void k_fconv(const float* __restrict__ src, uint2* __restrict__ hi,
                        uint2* __restrict__ lo, int n4) {
    int i = blockIdx.x*blockDim.x + threadIdx.x;
    if (i >= n4) return;
    float4 v = ((const float4*)src)[i];
    uint2 h, l; hilo4(v, h, l);
    hi[i] = h; lo[i] = l;
}
// src: nsub consecutive [128 k][128 n] slices -> dst [n][k] bf16 hi/lo
__global__ void k_wconv(const float* __restrict__ src, int dstblock, int nsub) {
    int i = blockIdx.x*blockDim.x + threadIdx.x;
    if (i >= nsub*16384) return;
    int sub = i >> 14, r = i & 16383, n = r >> 7, k = r & 127;
    float v = src[(size_t)sub*16384 + k*128 + n];
    __nv_bfloat16 h = __float2bfloat16_rn(v);
    __nv_bfloat16 l = __float2bfloat16_rn(v - __bfloat162float(h));
    size_t e = (size_t)(dstblock + sub)*16384 + n*128 + k;
    g_wbhi[e] = h; g_wblo[e] = l;
}

// ==================== k_proj: out = A @ W^T (+bias) ====================
__global__ __launch_bounds__(256, 1) void k_proj(const uint4* __restrict__ ahi,
                                                 const uint4* __restrict__ alo,
                                                 int wblock,
                                                 const float* __restrict__ bias,
                                                 float* __restrict__ outf,
                                                 __nv_bfloat16* __restrict__ outhi,
                                                 __nv_bfloat16* __restrict__ outlo) {
    extern __shared__ __nv_bfloat16 smb[];
    uint32_t sb = smem_u32(smb);
    int t = threadIdx.x, lane = t & 31, wid = t >> 5, wr = wid & 3, wc = wid >> 2;
    long base = (long)blockIdx.x*128;

    stage_w(smb, wblock, t);
    stage_a(smb, ahi, alo, nullptr, base, t);
    __syncthreads();
    float acc[2][8][4] = {};
    gemm3(sb, lane, wr, wc, acc);

    #pragma unroll
    for (int mi = 0; mi < 2; ++mi)
        #pragma unroll
        for (int hh = 0; hh < 2; ++hh) {
            long row = base + 32*wr + 16*mi + 8*hh + (lane >> 2);
            #pragma unroll
            for (int j = 0; j < 8; ++j) {
                int col = 64*wc + 8*j + 2*(lane & 3);
                float x = acc[mi][j][2*hh], y = acc[mi][j][2*hh + 1];
                if (bias) { x += bias[col]; y += bias[col + 1]; }
                if (outf) *(float2*)(outf + row*128 + col) = make_float2(x, y);
                if (outhi) {
                    uint32_t h, l; hilo2(x, y, h, l);
                    *(uint32_t*)(outhi + row*128 + col) = h;
                    *(uint32_t*)(outlo + row*128 + col) = l;
                }
            }
        }
}

// ==================== k_lv: K1,K2 -> logits ; Vh ====================
__global__ __launch_bounds__(256, 1) void k_lv(const int* __restrict__ E_idx,
                                               int bk1, int bk2, int bv0, int bv1) {
    extern __shared__ __nv_bfloat16 smb[];
    __shared__ int grow[128];
    uint32_t sb = smem_u32(smb);
    int t = threadIdx.x, lane = t & 31, wid = t >> 5, wr = wid & 3, wc = wid >> 2;
    long base = (long)blockIdx.x*128;

    if (t < 128) {
        long e = base + t;
        grow[t] = (int)(e/(LL*KK))*LL + E_idx[e];
    }
    stage_a(smb, g_hEhi, g_hElo, nullptr, base, t);
    stage_w(smb, bk1, t);
    __syncthreads();
    float acc1[2][8][4] = {};
    gemm3(sb, lane, wr, wc, acc1);               // K1 = hE @ Wk1
    __syncthreads();

    stage_a(smb, g_hVhi, g_hVlo, grow, 0, t);
    stage_w(smb, bk2, t);
    __syncthreads();
    float acc2[2][8][4] = {};
    gemm3(sb, lane, wr, wc, acc2);               // K2 = hKV @ Wk2

    // logits = sum_d Q*K1*K2 / 32 per head (head = 32 cols)
    #pragma unroll
    for (int mi = 0; mi < 2; ++mi)
        #pragma unroll
        for (int hh = 0; hh < 2; ++hh) {
            int r = 32*wr + 16*mi + 8*hh + (lane >> 2);
            long e = base + r;
            int node = (int)(e / KK), kk = (int)(e - (long)node*KK);
            const float* qrow = g_Q + (size_t)node*128;
            float s0 = 0.f, s1 = 0.f;
            #pragma unroll
            for (int j = 0; j < 8; ++j) {
                int col = 64*wc + 8*j + 2*(lane & 3);
                float2 q = *(const float2*)(qrow + col);
                float p = q.x*acc1[mi][j][2*hh]  *acc2[mi][j][2*hh]
                        + q.y*acc1[mi][j][2*hh+1]*acc2[mi][j][2*hh+1];
                if (j < 4) s0 += p; else s1 += p;
            }
            s0 += __shfl_xor_sync(0xffffffffu, s0, 1);
            s0 += __shfl_xor_sync(0xffffffffu, s0, 2);
            s1 += __shfl_xor_sync(0xffffffffu, s1, 1);
            s1 += __shfl_xor_sync(0xffffffffu, s1, 2);
            if ((lane & 3) == 0) {
                g_logits[((size_t)node*NHD + 2*wc    )*KK + kk] = s0*(1.f/32.f);
                g_logits[((size_t)node*NHD + 2*wc + 1)*KK + kk] = s1*(1.f/32.f);
            }
        }
    __syncthreads();

    stage_w(smb, bv1, t);                        // A stays hKV; Wv rows [128:256)
    __syncthreads();
    #pragma unroll
    for (int mi = 0; mi < 2; ++mi)
        #pragma unroll
        for (int j = 0; j < 8; ++j)
            #pragma unroll
            for (int q = 0; q < 4; ++q) acc1[mi][j][q] = 0.f;
    gemm3(sb, lane, wr, wc, acc1);               // Vh = hKV @ Wv1
    __syncthreads();

    stage_a(smb, g_hEhi, g_hElo, nullptr, base, t);
    stage_w(smb, bv0, t);                        // Wv rows [0:128)
    __syncthreads();
    gemm3(sb, lane, wr, wc, acc1);               // Vh += hE @ Wv0

    #pragma unroll
    for (int mi = 0; mi < 2; ++mi)
        #pragma unroll
        for (int hh = 0; hh < 2; ++hh) {
            long row = base + 32*wr + 16*mi + 8*hh + (lane >> 2);
            #pragma unroll
            for (int j = 0; j < 8; ++j) {
                int col = 64*wc + 8*j + 2*(lane & 3);
                *(float2*)(g_Vh + (size_t)row*128 + col) =
                    make_float2(acc1[mi][j][2*hh], acc1[mi][j][2*hh+1]);
            }
        }
}

// ==================== k_fc1: h_E = LN(relu([hE, hKV, hVself] @ fc1 + b)) ====
__global__ __launch_bounds__(256, 1) void k_fc1(const int* __restrict__ E_idx,
                                                const float* __restrict__ fc1b,
                                                const float* __restrict__ ng,
                                                const float* __restrict__ nb) {
    extern __shared__ __nv_bfloat16 smb[];
    __shared__ int grow[128], grow2[128];
    __shared__ float reds[256], reds2[256];
    uint32_t sb = smem_u32(smb);
    int t = threadIdx.x, lane = t & 31, wid = t >> 5, wr = wid & 3, wc = wid >> 2;
    long base = (long)blockIdx.x*128;

    if (t < 128) {
        long e = base + t;
        grow[t]  = (int)(e/(LL*KK))*LL + E_idx[e];
        grow2[t] = (int)(e / KK);
    }
    stage_a(smb, g_hEhi, g_hElo, nullptr, base, t);
    stage_w(smb, 20, t);
    __syncthreads();
    float acc[2][8][4] = {};
    gemm3(sb, lane, wr, wc, acc);
    __syncthreads();

    stage_a(smb, g_hVhi, g_hVlo, grow, 0, t);
    stage_w(smb, 21, t);
    __syncthreads();
    gemm3(sb, lane, wr, wc, acc);
    __syncthreads();

    stage_a(smb, g_hVhi, g_hVlo, grow2, 0, t);
    stage_w(smb, 22, t);
    __syncthreads();
    gemm3(sb, lane, wr, wc, acc);

    // relu + bias, row partial sums
    #pragma unroll
    for (int mi = 0; mi < 2; ++mi)
        #pragma unroll
        for (int hh = 0; hh < 2; ++hh) {
            int r = 32*wr + 16*mi + 8*hh + (lane >> 2);
            float s = 0.f, s2 = 0.f;
            #pragma unroll
            for (int j = 0; j < 8; ++j) {
                int col = 64*wc + 8*j + 2*(lane & 3);
                float x = fmaxf(acc[mi][j][2*hh]   + fc1b[col],     0.f);
                float y = fmaxf(acc[mi][j][2*hh+1] + fc1b[col + 1], 0.f);
                acc[mi][j][2*hh] = x; acc[mi][j][2*hh+1] = y;
                s += x + y; s2 += x*x + y*y;
            }
            s  += __shfl_xor_sync(0xffffffffu, s, 1);
            s  += __shfl_xor_sync(0xffffffffu, s, 2);
            s2 += __shfl_xor_sync(0xffffffffu, s2, 1);
            s2 += __shfl_xor_sync(0xffffffffu, s2, 2);
            if ((lane & 3) == 0) { reds[r*2 + wc] = s; reds2[r*2 + wc] = s2; }
        }
    __syncthreads();

    #pragma unroll
    for (int mi = 0; mi < 2; ++mi)
        #pragma unroll
        for (int hh = 0; hh < 2; ++hh) {
            int r = 32*wr + 16*mi + 8*hh + (lane >> 2);
            float s  = reds[r*2] + reds[r*2 + 1];
            float s2 = reds2[r*2] + reds2[r*2 + 1];
            float mu  = s*(1.f/128.f);
            float var = fmaxf((s2 - 128.f*mu*mu)*(1.f/127.f), 0.f);
            float rs  = 1.f/(sqrtf(var + EPSX) + EPSX);
            long row = base + r;
            #pragma unroll
            for (int j = 0; j < 8; ++j) {
                int col = 64*wc + 8*j + 2*(lane & 3);
                float x = ng[col    ]*(acc[mi][j][2*hh]   - mu)*rs + nb[col];
                float y = ng[col + 1]*(acc[mi][j][2*hh+1] - mu)*rs + nb[col + 1];
                uint32_t h, l; hilo2(x, y, h, l);
                *(uint32_t*)((__nv_bfloat16*)g_hEhi + (size_t)row*128 + col) = h;
                *(uint32_t*)((__nv_bfloat16*)g_hElo + (size_t)row*128 + col) = l;
            }
        }
}

// ==================== k_attn (fp32): softmax, attend*Vh, @Wo, residual+LN ====
__device__ __forceinline__ float2 ffma2(float2 d, float2 a, float2 b) {
    unsigned long long du = *reinterpret_cast<unsigned long long*>(&d);
    unsigned long long au = *reinterpret_cast<unsigned long long*>(&a);
    unsigned long long bu = *reinterpret_cast<unsigned long long*>(&b);
    asm("fma.rn.f32x2 %0, %1, %2, %0;" : "+l"(du) : "l"(au), "l"(bu));
    return *reinterpret_cast<float2*>(&du);
}
__device__ __forceinline__ void stage_mat128(float* ws, const float* __restrict__ W,
                                             int t, int nthreads) {
    for (int i = t; i < (128*128)/4; i += nthreads)
        reinterpret_cast<float4*>(ws)[i] = reinterpret_cast<const float4*>(W)[i];
}
__device__ __forceinline__ void tile_fma(const float* a_s, const float* w_s,
                                         int n0, int c0, float2 acc[4][2]) {
    #pragma unroll 8
    for (int j = 0; j < 128; ++j) {
        float2 w0 = *reinterpret_cast<const float2*>(&w_s[j*128 + c0]);
        float2 w1 = *reinterpret_cast<const float2*>(&w_s[j*128 + c0 + 2]);
        #pragma unroll
        for (int r = 0; r < 4; ++r) {
            float a = a_s[(n0 + r)*128 + j];
            float2 a2 = make_float2(a, a);
            acc[r][0] = ffma2(acc[r][0], a2, w0);
            acc[r][1] = ffma2(acc[r][1], a2, w1);
        }
    }
}

__global__ __launch_bounds__(256) void k_attn(const int* __restrict__ E_idx,
                                              const float* __restrict__ mask,
                                              const float* __restrict__ Wo,
                                              const float* __restrict__ lng,
                                              const float* __restrict__ lnb) {
    extern __shared__ float smf[];
    float* w_s = smf;
    float* a_s = smf + 128*128;
    __shared__ float att_s[32*NHD*KK];
    int t = threadIdx.x, tx = t & 31, ty = t >> 5;
    int n0 = ty*4, c0 = tx*4;
    int base = blockIdx.x*32;

    if (t < 128) {
        int nn = t >> 2, h = t & 3;
        int node = base + nn;
        int b = node / LL;
        float msel = mask[node];
        const int* eidx = &E_idx[node*KK];
        const float* lg = &g_logits[((size_t)node*NHD + h)*KK];
        float mk[KK], lv[KK];
        float mx = -3.4e38f;
        #pragma unroll
        for (int k = 0; k < KK; ++k) {
            int gi = b*LL + eidx[k];
            mk[k] = msel*mask[gi];
            lv[k] = lg[k];
            if (mk[k] > 0.f && lv[k] > mx) mx = lv[k];
        }
        float s = 0.f;
        #pragma unroll
        for (int k = 0; k < KK; ++k) {
            float e = (mk[k] > 0.f) ? __expf(lv[k] - mx) : 0.f;
            lv[k] = e; s += e;
        }
        float inv = (s > 0.f) ? (1.f/s) : 0.f;
        #pragma unroll
        for (int k = 0; k < KK; ++k)
            att_s[nn*(NHD*KK) + h*KK + k] = mk[k]*lv[k]*inv;
    }
    __syncthreads();

    #pragma unroll
    for (int r = 0; r < 4; ++r) {
        int nn = n0 + r;
        float4 u = make_float4(0.f, 0.f, 0.f, 0.f);
        const float* vh = &g_Vh[(size_t)(base + nn)*KK*128 + c0];
        const float* at = &att_s[nn*(NHD*KK) + (tx >> 3)*KK];
        #pragma unroll 6
        for (int k = 0; k < KK; ++k) {
            float a = at[k];
            float4 v = *reinterpret_cast<const float4*>(&vh[k*128]);
            u.x += a*v.x; u.y += a*v.y; u.z += a*v.z; u.w += a*v.w;
        }
        *reinterpret_cast<float4*>(&a_s[nn*128 + c0]) = u;
    }
    stage_mat128(w_s, Wo, t, 256);
    __syncthreads();

    float2 acc[4][2] = {};
    tile_fma(a_s, w_s, n0, c0, acc);

    float4 gv  = *reinterpret_cast<const float4*>(&lng[c0]);
    float4 bv2 = *reinterpret_cast<const float4*>(&lnb[c0]);
    #pragma unroll
    for (int r = 0; r < 4; ++r) {
        int node = base + n0 + r;
        float4 hv = *reinterpret_cast<const float4*>(&g_hV[node*128 + c0]);
        float x0 = hv.x + acc[r][0].x, x1 = hv.y + acc[r][0].y;
        float x2 = hv.z + acc[r][1].x, x3 = hv.w + acc[r][1].y;
        float s  = x0 + x1 + x2 + x3;
        float s2 = x0*x0 + x1*x1 + x2*x2 + x3*x3;
        #pragma unroll
        for (int o = 16; o > 0; o >>= 1) {
            s  += __shfl_xor_sync(0xffffffffu, s,  o);
            s2 += __shfl_xor_sync(0xffffffffu, s2, o);
        }
        float mu  = s*(1.f/128.f);
        float var = fmaxf((s2 - 128.f*mu*mu)*(1.f/127.f), 0.f);
        float rs  = 1.f/(sqrtf(var + EPSX) + EPSX);
        float m   = mask[node];
        float4 o4;
        o4.x = m*(gv.x*(x0 - mu)*rs + bv2.x);
        o4.y = m*(gv.y*(x1 - mu)*rs + bv2.y);
        o4.z = m*(gv.z*(x2 - mu)*rs + bv2.z);
        o4.w = m*(gv.w*(x3 - mu)*rs + bv2.w);
        *reinterpret_cast<float4*>(&g_hV[node*128 + c0]) = o4;
        uint2 h, l; hilo4(o4, h, l);
        *(uint2*)((__nv_bfloat16*)g_hVhi + (size_t)node*128 + c0) = h;
        *(uint2*)((__nv_bfloat16*)g_hVlo + (size_t)node*128 + c0) = l;
    }
}

__global__ void k_copy(float* __restrict__ out) {
    int i = blockIdx.x*blockDim.x + threadIdx.x;
    reinterpret_cast<float4*>(out)[i] = reinterpret_cast<const float4*>(g_hV)[i];
}

// =========================================================================
extern "C" void kernel_launch(void* const* d_in, const int* in_sizes, int n_in,
                              void* d_out, int out_size) {
    const float* V      = (const float*)d_in[0];
    const float* E      = (const float*)d_in[1];
    const int*   E_idx  = (const int*)  d_in[2];
    const float* mask   = (const float*)d_in[3];
    const float* Ws_w   = (const float*)d_in[4];
    const float* Ws_b   = (const float*)d_in[5];
    const float* Wt_w   = (const float*)d_in[6];
    const float* Wt_b   = (const float*)d_in[7];
    const float* Wq     = (const float*)d_in[8];
    const float* Wk1    = (const float*)d_in[9];
    const float* Wk2    = (const float*)d_in[10];
    const float* Wv     = (const float*)d_in[11];
    const float* Wo     = (const float*)d_in[12];
    const float* ln_g   = (const float*)d_in[13];
    const float* ln_b   = (const float*)d_in[14];
    const float* fc1_w  = (const float*)d_in[15];
    const float* fc1_b  = (const float*)d_in[16];
    const float* norm_g = (const float*)d_in[17];
    const float* norm_b = (const float*)d_in[18];

    const int SMA = (128*128 + 32*128)*4;
    cudaFuncSetAttribute(k_proj, cudaFuncAttributeMaxDynamicSharedMemorySize, SM_MMA);
    cudaFuncSetAttribute(k_lv,   cudaFuncAttributeMaxDynamicSharedMemorySize, SM_MMA);
    cudaFuncSetAttribute(k_fc1,  cudaFuncAttributeMaxDynamicSharedMemorySize, SM_MMA);
    cudaFuncSetAttribute(k_attn, cudaFuncAttributeMaxDynamicSharedMemorySize, SMA);

    void *phV, *pQ, *pVinh, *pVinl, *pEinh, *pEinl, *phVh, *phVl, *phEh, *phEl;
    cudaGetSymbolAddress(&phV,  g_hV);
    cudaGetSymbolAddress(&pQ,   g_Q);
    cudaGetSymbolAddress(&pVinh, g_Vinhi);  cudaGetSymbolAddress(&pVinl, g_Vinlo);
    cudaGetSymbolAddress(&pEinh, g_Einhi);  cudaGetSymbolAddress(&pEinl, g_Einlo);
    cudaGetSymbolAddress(&phVh, g_hVhi);    cudaGetSymbolAddress(&phVl, g_hVlo);
    cudaGetSymbolAddress(&phEh, g_hEhi);    cudaGetSymbolAddress(&phEl, g_hElo);

    // weight conversion: [k][n] fp32 -> [n][k] bf16 hi/lo
    k_wconv<<<(1*16384+255)/256, 256>>>(Ws_w,  0, 1);
    k_wconv<<<(1*16384+255)/256, 256>>>(Wt_w,  1, 1);
    k_wconv<<<(3*16384+255)/256, 256>>>(Wq,    2, 3);
    k_wconv<<<(3*16384+255)/256, 256>>>(Wk1,   5, 3);
    k_wconv<<<(3*16384+255)/256, 256>>>(Wk2,   8, 3);
    k_wconv<<<(6*16384+255)/256, 256>>>(Wv,   11, 6);
    k_wconv<<<(3*16384+255)/256, 256>>>(fc1_w, 20, 3);

    // input conversion
    k_fconv<<<(NNODE*32 + 255)/256, 256>>>(V, (uint2*)pVinh, (uint2*)pVinl, NNODE*32);
    k_fconv<<<(NE*32 + 255)/256, 256>>>(E, (uint2*)pEinh, (uint2*)pEinl, NE*32);

    // initial projections
    k_proj<<<NNODE/128, 256, SM_MMA>>>((const uint4*)pVinh, (const uint4*)pVinl, 0,
                                       Ws_b, (float*)phV,
                                       (__nv_bfloat16*)phVh, (__nv_bfloat16*)phVl);
    k_proj<<<NE/128, 256, SM_MMA>>>((const uint4*)pEinh, (const uint4*)pEinl, 1,
                                    Wt_b, nullptr,
                                    (__nv_bfloat16*)phEh, (__nv_bfloat16*)phEl);

    for (int i = 0; i < NLAY; ++i) {
        k_proj<<<NNODE/128, 256, SM_MMA>>>((const uint4*)phVh, (const uint4*)phVl,
                                           2 + i, nullptr, (float*)pQ, nullptr, nullptr);
        k_lv<<<NE/128, 256, SM_MMA>>>(E_idx, 5 + i, 8 + i, 11 + 2*i, 12 + 2*i);
        k_attn<<<NNODE/32, 256, SMA>>>(E_idx, mask, Wo + i*128*128,
                                       ln_g + i*128, ln_b + i*128);
        k_fc1<<<NE/128, 256, SM_MMA>>>(E_idx, fc1_b, norm_g, norm_b);
    }

    k_copy<<<(NNODE*128/4)/256, 256>>>((float*)d_out);
    (void)in_sizes; (void)n_in; (void)out_size;
}

// round 6
// speedup vs baseline: 3.9595x; 1.0260x over previous
#include <cuda_runtime.h>
#include <cuda_bf16.h>
#include <stdint.h>
#include <math.h>

#define BB 4
#define LL 2048
#define KK 30
#define NHD 4
#define NLAY 3
#define NNODE (BB*LL)        /* 8192   */
#define NE (NNODE*KK)        /* 245760 */
#define EPSX 1e-6f

// ==================== device scratch (static, no allocation) ====================
__device__ float g_hV[NNODE*128];
__device__ float g_Q[NNODE*128];
__device__ float g_Vh[(size_t)NE*128];
__device__ float g_logits[(size_t)NNODE*NHD*KK];
__device__ __nv_bfloat16 g_wbhi[23*16384], g_wblo[23*16384];   // weights [n][k] bf16
__device__ uint4 g_hVhi[NNODE*16], g_hVlo[NNODE*16];
__device__ uint4 g_Vinhi[NNODE*16], g_Vinlo[NNODE*16];
__device__ uint4 g_Einhi[(size_t)NE*16], g_Einlo[(size_t)NE*16];
__device__ uint4 g_hEhi[(size_t)NE*16],  g_hElo[(size_t)NE*16];

// ==================== helpers ====================
__device__ __forceinline__ uint32_t smem_u32(const void* p) {
    uint32_t a;
    asm("{ .reg .u64 tmp; cvta.to.shared.u64 tmp, %1; cvt.u32.u64 %0, tmp; }"
        : "=r"(a) : "l"(p));
    return a;
}
__device__ __forceinline__ void ldsm4(uint32_t r[4], uint32_t addr) {
    asm volatile("ldmatrix.sync.aligned.m8n8.x4.shared.b16 {%0,%1,%2,%3}, [%4];"
        : "=r"(r[0]), "=r"(r[1]), "=r"(r[2]), "=r"(r[3]) : "r"(addr));
}
__device__ __forceinline__ void mma16816(float c[4], const uint32_t a[4], const uint32_t b[2]) {
    asm volatile("mma.sync.aligned.m16n8k16.row.col.f32.bf16.bf16.f32 "
        "{%0,%1,%2,%3}, {%4,%5,%6,%7}, {%8,%9}, {%0,%1,%2,%3};"
        : "+f"(c[0]), "+f"(c[1]), "+f"(c[2]), "+f"(c[3])
        : "r"(a[0]), "r"(a[1]), "r"(a[2]), "r"(a[3]), "r"(b[0]), "r"(b[1]));
}
__device__ __forceinline__ void hilo2(float x, float y, uint32_t& h, uint32_t& l) {
    __nv_bfloat16 hx = __float2bfloat16_rn(x), hy = __float2bfloat16_rn(y);
    __nv_bfloat16 lx = __float2bfloat16_rn(x - __bfloat162float(hx));
    __nv_bfloat16 ly = __float2bfloat16_rn(y - __bfloat162float(hy));
    h = (uint32_t)__bfloat16_as_ushort(hx) | ((uint32_t)__bfloat16_as_ushort(hy) << 16);
    l = (uint32_t)__bfloat16_as_ushort(lx) | ((uint32_t)__bfloat16_as_ushort(ly) << 16);
}
__device__ __forceinline__ void hilo4(float4 v, uint2& h, uint2& l) {
    hilo2(v.x, v.y, h.x, l.x);
    hilo2(v.z, v.w, h.y, l.y);
}
__device__ __forceinline__ void cpa16(uint32_t dst, const void* src) {
    asm volatile("cp.async.cg.shared.global [%0], [%1], 16;" :: "r"(dst), "l"(src) : "memory");
}
#define CP_COMMIT() asm volatile("cp.async.commit_group;" ::: "memory")
#define CP_WAIT0()  asm volatile("cp.async.wait_group 0;" ::: "memory")

// ==================== smem layout: padded rows 272B (136 bf16) ====================
#define ABYTES (128*272)        /* 34816 one 128x128 bf16 padded tile */
#define OFF_A   0                                /* A: hi, lo            */
#define OFF_W0  (2*ABYTES)                       /* W buffer 0: hi, lo   */
#define OFF_W1  (4*ABYTES)                       /* W buffer 1: hi, lo   */
#define SM_PIPE (6*ABYTES)                       /* 208896 bytes         */
#define SM_ONE  (4*ABYTES)                       /* k_proj: A + one W    */

// async stagers (256 threads, 2048 16B chunks per hi/lo pair)
__device__ __forceinline__ void stage_a_cp(uint32_t sb, const uint4* ghi,
                                           const uint4* glo, const int* grow,
                                           long base, int t) {
    #pragma unroll
    for (int i = 0; i < 8; ++i) {
        int idx = t + 256*i;
        int row = idx >> 4, c = idx & 15;
        long gr = grow ? (long)grow[row] : (base + row);
        uint32_t d = (uint32_t)(row*272 + c*16);
        cpa16(sb + OFF_A + d,          ghi + gr*16 + c);
        cpa16(sb + OFF_A + ABYTES + d, glo + gr*16 + c);
    }
}
__device__ __forceinline__ void stage_w_cp(uint32_t sb, uint32_t woff, int block, int t) {
    const uint4* sh = (const uint4*)(g_wbhi + (size_t)block*16384);
    const uint4* sl = (const uint4*)(g_wblo + (size_t)block*16384);
    #pragma unroll
    for (int i = 0; i < 8; ++i) {
        int idx = t + 256*i;
        int row = idx >> 4, c = idx & 15;
        uint32_t d = (uint32_t)(row*272 + c*16);
        cpa16(sb + woff + d,          sh + idx);
        cpa16(sb + woff + ABYTES + d, sl + idx);
    }
}

// 3-term split GEMM: acc += A(hi+lo) @ W(hi+lo)^T (dropping lo*lo)
// warp tile 32x64: rows 32*wr.., cols 64*wc..
__device__ __forceinline__ void gemm3(uint32_t sb, uint32_t woff, int lane, int wr, int wc,
                                      float acc[2][8][4]) {
    uint32_t arow = (uint32_t)(32*wr + (lane & 15));
    uint32_t acol = (uint32_t)((lane >> 4) << 3);
    uint32_t brow = (uint32_t)(64*wc + (lane & 7) + ((lane >> 4) << 3));
    uint32_t bcol = (uint32_t)(((lane >> 3) & 1) << 3);
    #pragma unroll 2
    for (int ks = 0; ks < 8; ++ks) {
        uint32_t k0 = (uint32_t)(ks*16);
        uint32_t ah[2][4], al[2][4];
        #pragma unroll
        for (int mi = 0; mi < 2; ++mi) {
            uint32_t off = ((arow + 16u*mi)*136u + k0 + acol)*2u;
            ldsm4(ah[mi], sb + OFF_A + off);
            ldsm4(al[mi], sb + OFF_A + ABYTES + off);
        }
        uint32_t bh[8][2], bl[8][2];
        #pragma unroll
        for (int jp = 0; jp < 4; ++jp) {
            uint32_t off = ((brow + 16u*jp)*136u + k0 + bcol)*2u;
            uint32_t r[4];
            ldsm4(r, sb + woff + off);
            bh[2*jp][0] = r[0]; bh[2*jp][1] = r[1];
            bh[2*jp+1][0] = r[2]; bh[2*jp+1][1] = r[3];
            ldsm4(r, sb + woff + ABYTES + off);
            bl[2*jp][0] = r[0]; bl[2*jp][1] = r[1];
            bl[2*jp+1][0] = r[2]; bl[2*jp+1][1] = r[3];
        }
        #pragma unroll
        for (int mi = 0; mi < 2; ++mi)
            #pragma unroll
            for (int j = 0; j < 8; ++j) {
                mma16816(acc[mi][j], ah[mi], bh[j]);
                mma16816(acc[mi][j], ah[mi], bl[j]);
                mma16816(acc[mi][j], al[mi], bh[j]);
            }
    }
}

// ==================== conversion kernels ====================
__global__ void k_fconv(const float* __restrict__ src, uint2* __restrict__ hi,
                        uint2* __restrict__ lo, int n4) {
    int i = blockIdx.x*blockDim.x + threadIdx.x;
    if (i >= n4) return;
    float4 v = ((const float4*)src)[i];
    uint2 h, l; hilo4(v, h, l);
    hi[i] = h; lo[i] = l;
}
__global__ void k_wconv(const float* __restrict__ src, int dstblock, int nsub) {
    int i = blockIdx.x*blockDim.x + threadIdx.x;
    if (i >= nsub*16384) return;
    int sub = i >> 14, r = i & 16383, n = r >> 7, k = r & 127;
    float v = src[(size_t)sub*16384 + k*128 + n];
    __nv_bfloat16 h = __float2bfloat16_rn(v);
    __nv_bfloat16 l = __float2bfloat16_rn(v - __bfloat162float(h));
    size_t e = (size_t)(dstblock + sub)*16384 + n*128 + k;
    g_wbhi[e] = h; g_wblo[e] = l;
}

// ==================== k_proj: out = A @ W^T (+bias), single phase ====
__global__ __launch_bounds__(256, 1) void k_proj(const uint4* __restrict__ ahi,
                                                 const uint4* __restrict__ alo,
                                                 int wblock,
                                                 const float* __restrict__ bias,
                                                 float* __restrict__ outf,
                                                 __nv_bfloat16* __restrict__ outhi,
                                                 __nv_bfloat16* __restrict__ outlo) {
    extern __shared__ char smc[];
    uint32_t sb = smem_u32(smc);
    int t = threadIdx.x, lane = t & 31, wid = t >> 5, wr = wid & 3, wc = wid >> 2;
    long base = (long)blockIdx.x*128;

    stage_w_cp(sb, OFF_W0, wblock, t);
    stage_a_cp(sb, ahi, alo, nullptr, base, t);
    CP_COMMIT(); CP_WAIT0();
    __syncthreads();
    float acc[2][8][4] = {};
    gemm3(sb, OFF_W0, lane, wr, wc, acc);

    #pragma unroll
    for (int mi = 0; mi < 2; ++mi)
        #pragma unroll
        for (int hh = 0; hh < 2; ++hh) {
            long row = base + 32*wr + 16*mi + 8*hh + (lane >> 2);
            #pragma unroll
            for (int j = 0; j < 8; ++j) {
                int col = 64*wc + 8*j + 2*(lane & 3);
                float x = acc[mi][j][2*hh], y = acc[mi][j][2*hh + 1];
                if (bias) { x += bias[col]; y += bias[col + 1]; }
                if (outf) *(float2*)(outf + row*128 + col) = make_float2(x, y);
                if (outhi) {
                    uint32_t h, l; hilo2(x, y, h, l);
                    *(uint32_t*)(outhi + row*128 + col) = h;
                    *(uint32_t*)(outlo + row*128 + col) = l;
                }
            }
        }
}

// ==================== k_lv: K1, Vh(hE), K2+logits, Vh(hKV) — W double-buffered ====
__global__ __launch_bounds__(256, 1) void k_lv(const int* __restrict__ E_idx,
                                               int bk1, int bk2, int bv0, int bv1) {
    extern __shared__ char smc[];
    __shared__ int grow[128];
    uint32_t sb = smem_u32(smc);
    int t = threadIdx.x, lane = t & 31, wid = t >> 5, wr = wid & 3, wc = wid >> 2;
    long base = (long)blockIdx.x*128;

    if (t < 128) {
        long e = base + t;
        grow[t] = (int)(e/(LL*KK))*LL + E_idx[e];
    }
    stage_a_cp(sb, g_hEhi, g_hElo, nullptr, base, t);
    stage_w_cp(sb, OFF_W0, bk1, t);
    CP_COMMIT(); CP_WAIT0();
    __syncthreads();                              // grow also visible now

    stage_w_cp(sb, OFF_W1, bv0, t); CP_COMMIT();  // prefetch Wv0 under K1
    float acc1[2][8][4] = {};
    gemm3(sb, OFF_W0, lane, wr, wc, acc1);        // K1 = hE @ Wk1
    CP_WAIT0(); __syncthreads();

    stage_w_cp(sb, OFF_W0, bk2, t); CP_COMMIT();  // prefetch Wk2 under Vh0
    float accv[2][8][4] = {};
    gemm3(sb, OFF_W1, lane, wr, wc, accv);        // Vh = hE @ Wv0
    CP_WAIT0(); __syncthreads();

    stage_a_cp(sb, g_hVhi, g_hVlo, grow, 0, t);   // A <- gathered hV (exposed)
    CP_COMMIT(); CP_WAIT0();
    __syncthreads();

    stage_w_cp(sb, OFF_W1, bv1, t); CP_COMMIT();  // prefetch Wv1 under K2
    float acc2[2][8][4] = {};
    gemm3(sb, OFF_W0, lane, wr, wc, acc2);        // K2 = hKV @ Wk2

    // logits = sum_d Q*K1*K2 / 32 per head (head = 32 cols)
    #pragma unroll
    for (int mi = 0; mi < 2; ++mi)
        #pragma unroll
        for (int hh = 0; hh < 2; ++hh) {
            int r = 32*wr + 16*mi + 8*hh + (lane >> 2);
            long e = base + r;
            int node = (int)(e / KK), kk = (int)(e - (long)node*KK);
            const float* qrow = g_Q + (size_t)node*128;
            float s0 = 0.f, s1 = 0.f;
            #pragma unroll
            for (int j = 0; j < 8; ++j) {
                int col = 64*wc + 8*j + 2*(lane & 3);
                float2 q = *(const float2*)(qrow + col);
                float p = q.x*acc1[mi][j][2*hh]  *acc2[mi][j][2*hh]
                        + q.y*acc1[mi][j][2*hh+1]*acc2[mi][j][2*hh+1];
                if (j < 4) s0 += p; else s1 += p;
            }
            s0 += __shfl_xor_sync(0xffffffffu, s0, 1);
            s0 += __shfl_xor_sync(0xffffffffu, s0, 2);
            s1 += __shfl_xor_sync(0xffffffffu, s1, 1);
            s1 += __shfl_xor_sync(0xffffffffu, s1, 2);
            if ((lane & 3) == 0) {
                g_logits[((size_t)node*NHD + 2*wc    )*KK + kk] = s0*(1.f/32.f);
                g_logits[((size_t)node*NHD + 2*wc + 1)*KK + kk] = s1*(1.f/32.f);
            }
        }
    CP_WAIT0(); __syncthreads();

    gemm3(sb, OFF_W1, lane, wr, wc, accv);        // Vh += hKV @ Wv1

    #pragma unroll
    for (int mi = 0; mi < 2; ++mi)
        #pragma unroll
        for (int hh = 0; hh < 2; ++hh) {
            long row = base + 32*wr + 16*mi + 8*hh + (lane >> 2);
            #pragma unroll
            for (int j = 0; j < 8; ++j) {
                int col = 64*wc + 8*j + 2*(lane & 3);
                *(float2*)(g_Vh + (size_t)row*128 + col) =
                    make_float2(accv[mi][j][2*hh], accv[mi][j][2*hh+1]);
            }
        }
}

// ==================== k_fc1: h_E = LN(relu([hE, hKV, hVself] @ fc1 + b)) ====
__global__ __launch_bounds__(256, 1) void k_fc1(const int* __restrict__ E_idx,
                                                const float* __restrict__ fc1b,
                                                const float* __restrict__ ng,
                                                const float* __restrict__ nb) {
    extern __shared__ char smc[];
    __shared__ int grow[128], grow2[128];
    __shared__ float reds[256], reds2[256];
    uint32_t sb = smem_u32(smc);
    int t = threadIdx.x, lane = t & 31, wid = t >> 5, wr = wid & 3, wc = wid >> 2;
    long base = (long)blockIdx.x*128;

    if (t < 128) {
        long e = base + t;
        grow[t]  = (int)(e/(LL*KK))*LL + E_idx[e];
        grow2[t] = (int)(e / KK);
    }
    stage_a_cp(sb, g_hEhi, g_hElo, nullptr, base, t);
    stage_w_cp(sb, OFF_W0, 20, t);
    CP_COMMIT(); CP_WAIT0();
    __syncthreads();

    stage_w_cp(sb, OFF_W1, 21, t); CP_COMMIT();   // prefetch chunk-1 W
    float acc[2][8][4] = {};
    gemm3(sb, OFF_W0, lane, wr, wc, acc);
    CP_WAIT0(); __syncthreads();

    stage_a_cp(sb, g_hVhi, g_hVlo, grow, 0, t);   // A <- gathered hV (exposed)
    stage_w_cp(sb, OFF_W0, 22, t);                // chunk-2 W alongside
    CP_COMMIT(); CP_WAIT0();
    __syncthreads();

    gemm3(sb, OFF_W1, lane, wr, wc, acc);
    __syncthreads();

    stage_a_cp(sb, g_hVhi, g_hVlo, grow2, 0, t);  // A <- self hV (exposed)
    CP_COMMIT(); CP_WAIT0();
    __syncthreads();

    gemm3(sb, OFF_W0, lane, wr, wc, acc);

    // relu + bias, row partial sums
    #pragma unroll
    for (int mi = 0; mi < 2; ++mi)
        #pragma unroll
        for (int hh = 0; hh < 2; ++hh) {
            int r = 32*wr + 16*mi + 8*hh + (lane >> 2);
            float s = 0.f, s2 = 0.f;
            #pragma unroll
            for (int j = 0; j < 8; ++j) {
                int col = 64*wc + 8*j + 2*(lane & 3);
                float x = fmaxf(acc[mi][j][2*hh]   + fc1b[col],     0.f);
                float y = fmaxf(acc[mi][j][2*hh+1] + fc1b[col + 1], 0.f);
                acc[mi][j][2*hh] = x; acc[mi][j][2*hh+1] = y;
                s += x + y; s2 += x*x + y*y;
            }
            s  += __shfl_xor_sync(0xffffffffu, s, 1);
            s  += __shfl_xor_sync(0xffffffffu, s, 2);
            s2 += __shfl_xor_sync(0xffffffffu, s2, 1);
            s2 += __shfl_xor_sync(0xffffffffu, s2, 2);
            if ((lane & 3) == 0) { reds[r*2 + wc] = s; reds2[r*2 + wc] = s2; }
        }
    __syncthreads();

    #pragma unroll
    for (int mi = 0; mi < 2; ++mi)
        #pragma unroll
        for (int hh = 0; hh < 2; ++hh) {
            int r = 32*wr + 16*mi + 8*hh + (lane >> 2);
            float s  = reds[r*2] + reds[r*2 + 1];
            float s2 = reds2[r*2] + reds2[r*2 + 1];
            float mu  = s*(1.f/128.f);
            float var = fmaxf((s2 - 128.f*mu*mu)*(1.f/127.f), 0.f);
            float rs  = 1.f/(sqrtf(var + EPSX) + EPSX);
            long row = base + r;
            #pragma unroll
            for (int j = 0; j < 8; ++j) {
                int col = 64*wc + 8*j + 2*(lane & 3);
                float x = ng[col    ]*(acc[mi][j][2*hh]   - mu)*rs + nb[col];
                float y = ng[col + 1]*(acc[mi][j][2*hh+1] - mu)*rs + nb[col + 1];
                uint32_t h, l; hilo2(x, y, h, l);
                *(uint32_t*)((__nv_bfloat16*)g_hEhi + (size_t)row*128 + col) = h;
                *(uint32_t*)((__nv_bfloat16*)g_hElo + (size_t)row*128 + col) = l;
            }
        }
}

// ==================== k_attn (fp32): softmax, attend*Vh, @Wo, residual+LN ====
__device__ __forceinline__ float2 ffma2(float2 d, float2 a, float2 b) {
    unsigned long long du = *reinterpret_cast<unsigned long long*>(&d);
    unsigned long long au = *reinterpret_cast<unsigned long long*>(&a);
    unsigned long long bu = *reinterpret_cast<unsigned long long*>(&b);
    asm("fma.rn.f32x2 %0, %1, %2, %0;" : "+l"(du) : "l"(au), "l"(bu));
    return *reinterpret_cast<float2*>(&du);
}
__device__ __forceinline__ void stage_mat128(float* ws, const float* __restrict__ W,
                                             int t, int nthreads) {
    for (int i = t; i < (128*128)/4; i += nthreads)
        reinterpret_cast<float4*>(ws)[i] = reinterpret_cast<const float4*>(W)[i];
}
__device__ __forceinline__ void tile_fma(const float* a_s, const float* w_s,
                                         int n0, int c0, float2 acc[4][2]) {
    #pragma unroll 8
    for (int j = 0; j < 128; ++j) {
        float2 w0 = *reinterpret_cast<const float2*>(&w_s[j*128 + c0]);
        float2 w1 = *reinterpret_cast<const float2*>(&w_s[j*128 + c0 + 2]);
        #pragma unroll
        for (int r = 0; r < 4; ++r) {
            float a = a_s[(n0 + r)*128 + j];
            float2 a2 = make_float2(a, a);
            acc[r][0] = ffma2(acc[r][0], a2, w0);
            acc[r][1] = ffma2(acc[r][1], a2, w1);
        }
    }
}

__global__ __launch_bounds__(256) void k_attn(const int* __restrict__ E_idx,
                                              const float* __restrict__ mask,
                                              const float* __restrict__ Wo,
                                              const float* __restrict__ lng,
                                              const float* __restrict__ lnb) {
    extern __shared__ float smf[];
    float* w_s = smf;
    float* a_s = smf + 128*128;
    __shared__ float att_s[32*NHD*KK];
    int t = threadIdx.x, tx = t & 31, ty = t >> 5;
    int n0 = ty*4, c0 = tx*4;
    int base = blockIdx.x*32;

    if (t < 128) {
        int nn = t >> 2, h = t & 3;
        int node = base + nn;
        int b = node / LL;
        float msel = mask[node];
        const int* eidx = &E_idx[node*KK];
        const float* lg = &g_logits[((size_t)node*NHD + h)*KK];
        float mk[KK], lv[KK];
        float mx = -3.4e38f;
        #pragma unroll
        for (int k = 0; k < KK; ++k) {
            int gi = b*LL + eidx[k];
            mk[k] = msel*mask[gi];
            lv[k] = lg[k];
            if (mk[k] > 0.f && lv[k] > mx) mx = lv[k];
        }
        float s = 0.f;
        #pragma unroll
        for (int k = 0; k < KK; ++k) {
            float e = (mk[k] > 0.f) ? __expf(lv[k] - mx) : 0.f;
            lv[k] = e; s += e;
        }
        float inv = (s > 0.f) ? (1.f/s) : 0.f;
        #pragma unroll
        for (int k = 0; k < KK; ++k)
            att_s[nn*(NHD*KK) + h*KK + k] = mk[k]*lv[k]*inv;
    }
    __syncthreads();

    #pragma unroll
    for (int r = 0; r < 4; ++r) {
        int nn = n0 + r;
        float4 u = make_float4(0.f, 0.f, 0.f, 0.f);
        const float* vh = &g_Vh[(size_t)(base + nn)*KK*128 + c0];
        const float* at = &att_s[nn*(NHD*KK) + (tx >> 3)*KK];
        #pragma unroll 6
        for (int k = 0; k < KK; ++k) {
            float a = at[k];
            float4 v = *reinterpret_cast<const float4*>(&vh[k*128]);
            u.x += a*v.x; u.y += a*v.y; u.z += a*v.z; u.w += a*v.w;
        }
        *reinterpret_cast<float4*>(&a_s[nn*128 + c0]) = u;
    }
    stage_mat128(w_s, Wo, t, 256);
    __syncthreads();

    float2 acc[4][2] = {};
    tile_fma(a_s, w_s, n0, c0, acc);

    float4 gv  = *reinterpret_cast<const float4*>(&lng[c0]);
    float4 bv2 = *reinterpret_cast<const float4*>(&lnb[c0]);
    #pragma unroll
    for (int r = 0; r < 4; ++r) {
        int node = base + n0 + r;
        float4 hv = *reinterpret_cast<const float4*>(&g_hV[node*128 + c0]);
        float x0 = hv.x + acc[r][0].x, x1 = hv.y + acc[r][0].y;
        float x2 = hv.z + acc[r][1].x, x3 = hv.w + acc[r][1].y;
        float s  = x0 + x1 + x2 + x3;
        float s2 = x0*x0 + x1*x1 + x2*x2 + x3*x3;
        #pragma unroll
        for (int o = 16; o > 0; o >>= 1) {
            s  += __shfl_xor_sync(0xffffffffu, s,  o);
            s2 += __shfl_xor_sync(0xffffffffu, s2, o);
        }
        float mu  = s*(1.f/128.f);
        float var = fmaxf((s2 - 128.f*mu*mu)*(1.f/127.f), 0.f);
        float rs  = 1.f/(sqrtf(var + EPSX) + EPSX);
        float m   = mask[node];
        float4 o4;
        o4.x = m*(gv.x*(x0 - mu)*rs + bv2.x);
        o4.y = m*(gv.y*(x1 - mu)*rs + bv2.y);
        o4.z = m*(gv.z*(x2 - mu)*rs + bv2.z);
        o4.w = m*(gv.w*(x3 - mu)*rs + bv2.w);
        *reinterpret_cast<float4*>(&g_hV[node*128 + c0]) = o4;
        uint2 h, l; hilo4(o4, h, l);
        *(uint2*)((__nv_bfloat16*)g_hVhi + (size_t)node*128 + c0) = h;
        *(uint2*)((__nv_bfloat16*)g_hVlo + (size_t)node*128 + c0) = l;
    }
}

__global__ void k_copy(float* __restrict__ out) {
    int i = blockIdx.x*blockDim.x + threadIdx.x;
    reinterpret_cast<float4*>(out)[i] = reinterpret_cast<const float4*>(g_hV)[i];
}

// =========================================================================
extern "C" void kernel_launch(void* const* d_in, const int* in_sizes, int n_in,
                              void* d_out, int out_size) {
    const float* V      = (const float*)d_in[0];
    const float* E      = (const float*)d_in[1];
    const int*   E_idx  = (const int*)  d_in[2];
    const float* mask   = (const float*)d_in[3];
    const float* Ws_w   = (const float*)d_in[4];
    const float* Ws_b   = (const float*)d_in[5];
    const float* Wt_w   = (const float*)d_in[6];
    const float* Wt_b   = (const float*)d_in[7];
    const float* Wq     = (const float*)d_in[8];
    const float* Wk1    = (const float*)d_in[9];
    const float* Wk2    = (const float*)d_in[10];
    const float* Wv     = (const float*)d_in[11];
    const float* Wo     = (const float*)d_in[12];
    const float* ln_g   = (const float*)d_in[13];
    const float* ln_b   = (const float*)d_in[14];
    const float* fc1_w  = (const float*)d_in[15];
    const float* fc1_b  = (const float*)d_in[16];
    const float* norm_g = (const float*)d_in[17];
    const float* norm_b = (const float*)d_in[18];

    const int SMA = (128*128 + 32*128)*4;
    cudaFuncSetAttribute(k_proj, cudaFuncAttributeMaxDynamicSharedMemorySize, SM_ONE);
    cudaFuncSetAttribute(k_lv,   cudaFuncAttributeMaxDynamicSharedMemorySize, SM_PIPE);
    cudaFuncSetAttribute(k_fc1,  cudaFuncAttributeMaxDynamicSharedMemorySize, SM_PIPE);
    cudaFuncSetAttribute(k_attn, cudaFuncAttributeMaxDynamicSharedMemorySize, SMA);

    void *phV, *pQ, *pVinh, *pVinl, *pEinh, *pEinl, *phVh, *phVl, *phEh, *phEl;
    cudaGetSymbolAddress(&phV,  g_hV);
    cudaGetSymbolAddress(&pQ,   g_Q);
    cudaGetSymbolAddress(&pVinh, g_Vinhi);  cudaGetSymbolAddress(&pVinl, g_Vinlo);
    cudaGetSymbolAddress(&pEinh, g_Einhi);  cudaGetSymbolAddress(&pEinl, g_Einlo);
    cudaGetSymbolAddress(&phVh, g_hVhi);    cudaGetSymbolAddress(&phVl, g_hVlo);
    cudaGetSymbolAddress(&phEh, g_hEhi);    cudaGetSymbolAddress(&phEl, g_hElo);

    // weight conversion: [k][n] fp32 -> [n][k] bf16 hi/lo
    k_wconv<<<(1*16384+255)/256, 256>>>(Ws_w,  0, 1);
    k_wconv<<<(1*16384+255)/256, 256>>>(Wt_w,  1, 1);
    k_wconv<<<(3*16384+255)/256, 256>>>(Wq,    2, 3);
    k_wconv<<<(3*16384+255)/256, 256>>>(Wk1,   5, 3);
    k_wconv<<<(3*16384+255)/256, 256>>>(Wk2,   8, 3);
    k_wconv<<<(6*16384+255)/256, 256>>>(Wv,   11, 6);
    k_wconv<<<(3*16384+255)/256, 256>>>(fc1_w, 20, 3);

    // input conversion
    k_fconv<<<(NNODE*32 + 255)/256, 256>>>(V, (uint2*)pVinh, (uint2*)pVinl, NNODE*32);
    k_fconv<<<(NE*32 + 255)/256, 256>>>(E, (uint2*)pEinh, (uint2*)pEinl, NE*32);

    // initial projections
    k_proj<<<NNODE/128, 256, SM_ONE>>>((const uint4*)pVinh, (const uint4*)pVinl, 0,
                                       Ws_b, (float*)phV,
                                       (__nv_bfloat16*)phVh, (__nv_bfloat16*)phVl);
    k_proj<<<NE/128, 256, SM_ONE>>>((const uint4*)pEinh, (const uint4*)pEinl, 1,
                                    Wt_b, nullptr,
                                    (__nv_bfloat16*)phEh, (__nv_bfloat16*)phEl);

    for (int i = 0; i < NLAY; ++i) {
        k_proj<<<NNODE/128, 256, SM_ONE>>>((const uint4*)phVh, (const uint4*)phVl,
                                           2 + i, nullptr, (float*)pQ, nullptr, nullptr);
        k_lv<<<NE/128, 256, SM_PIPE>>>(E_idx, 5 + i, 8 + i, 11 + 2*i, 12 + 2*i);
        k_attn<<<NNODE/32, 256, SMA>>>(E_idx, mask, Wo + i*128*128,
                                       ln_g + i*128, ln_b + i*128);
        k_fc1<<<NE/128, 256, SM_PIPE>>>(E_idx, fc1_b, norm_g, norm_b);
    }

    k_copy<<<(NNODE*128/4)/256, 256>>>((float*)d_out);
    (void)in_sizes; (void)n_in; (void)out_size;
}